// round 15
// baseline (speedup 1.0000x reference)
#include <cuda_runtime.h>
#include <cuda_fp16.h>

#define NN   50000
#define NE   600000
#define FD   128
#define NG   256
#define HIDN 256
#define ODIM 16
#define MAXD 10
#define SCB  512
#define NSCB ((NN + SCB - 1) / SCB)
#define NT   ((NN + 127) / 128)        // 391 M-tiles (mf)
#define NT2  ((NN + 63) / 64)          // 782 M-tiles (pq)
#define SP   136                       // padded smem row stride (halfs)
#define SPB  (SP * 2)                  // 272 bytes
#define TILEB (128 * SPB)              // 34816 B per 128x128 tile
#define TIL64 (64 * SPB)               // 17408 B per 64x128 tile
#define B256B (256 * SPB)              // 69632 B per 256x128 tile
#define GTP  256                       // pq GEMM threads
#define GTM  256                       // mf GEMM threads

typedef unsigned long long u64;
typedef unsigned int u32;

// ---------------- scratch ----------------
__device__ int   g_degraw[NN];
__device__ int   g_off[NN + 1];
__device__ int   g_cursor[NN];
__device__ int   g_srcv[NE];
__device__ int   g_bcnt[MAXD + 1];
__device__ int   g_boff[MAXD + 2];
__device__ int   g_bcur[MAXD + 1];
__device__ int   g_bnodes[NN];
__device__ int   g_bsum[NSCB];
__device__ float g_X[NN * FD];
__device__ float g_H[NN * FD];
__device__ float g_E[NN * FD];
__device__ float g_P[NN * FD];
__device__ float g_Q[NN * FD];
__device__ float g_G[NG * 2 * FD];
__device__ __half g_Bpq[256 * FD];                 // [n=256][k=128]
__device__ __half g_Bmf[(MAXD + 1) * FD * 256];    // [d][n=128][k=256]

// ---------------- helpers ----------------
__device__ __forceinline__ u32 s2u(const void* p) {
    u32 a; asm("{ .reg .u64 t; cvta.to.shared.u64 t, %1; cvt.u32.u64 %0, t; }" : "=r"(a) : "l"(p));
    return a;
}
__device__ __forceinline__ void ldmx4(u32* r, u32 addr) {
    asm volatile("ldmatrix.sync.aligned.m8n8.x4.shared.b16 {%0,%1,%2,%3}, [%4];"
                 : "=r"(r[0]), "=r"(r[1]), "=r"(r[2]), "=r"(r[3]) : "r"(addr));
}
__device__ __forceinline__ void mmah(float* d, const u32* a, u32 b0, u32 b1) {
    asm volatile("mma.sync.aligned.m16n8k16.row.col.f32.f16.f16.f32 "
                 "{%0,%1,%2,%3}, {%4,%5,%6,%7}, {%8,%9}, {%0,%1,%2,%3};"
                 : "+f"(d[0]), "+f"(d[1]), "+f"(d[2]), "+f"(d[3])
                 : "r"(a[0]), "r"(a[1]), "r"(a[2]), "r"(a[3]), "r"(b0), "r"(b1));
}
__device__ __forceinline__ void cpa16(u32 saddr, const void* g) {
    asm volatile("cp.async.cg.shared.global [%0], [%1], 16;"
                 :: "r"(saddr), "l"(g) : "memory");
}
__device__ __forceinline__ void cpa_fence() {
    asm volatile("cp.async.commit_group;" ::: "memory");
    asm volatile("cp.async.wait_group 0;" ::: "memory");
}
// split float4 -> fp16 hi (2 u32) and lo (2 u32)
__device__ __forceinline__ void split4h(float4 v, uint2& hi, uint2& lo) {
    __half h0 = __float2half(v.x), h1 = __float2half(v.y);
    __half h2 = __float2half(v.z), h3 = __float2half(v.w);
    __half2 H0 = __halves2half2(h0, h1);
    __half2 H1 = __halves2half2(h2, h3);
    __half2 L0 = __halves2half2(__float2half(v.x - __half2float(h0)),
                                __float2half(v.y - __half2float(h1)));
    __half2 L1 = __halves2half2(__float2half(v.z - __half2float(h2)),
                                __float2half(v.w - __half2float(h3)));
    hi.x = *(u32*)&H0; hi.y = *(u32*)&H1;
    lo.x = *(u32*)&L0; lo.y = *(u32*)&L1;
}

// ---------------- prep ----------------
__global__ void k_initW(const float* __restrict__ Wedge, const float* __restrict__ Wlin,
                        const float* __restrict__ Wroot) {
    int i = blockIdx.x * 256 + threadIdx.x;
    if (i < NN) { g_degraw[i] = 0; g_cursor[i] = 0; }
    if (i <= MAXD) { g_bcnt[i] = 0; g_bcur[i] = 0; }
    if (i < 256 * FD) {
        int n = i / FD, k = i % FD;
        float v = (n < FD) ? (Wedge[k * FD + n] - Wedge[(k + FD) * FD + n])
                           : Wedge[(k + FD) * FD + (n - FD)];
        g_Bpq[i] = __float2half(v);
    }
    if (i < (MAXD + 1) * FD * 256) {
        int d = i / (FD * 256), r = i % (FD * 256);
        int n = r / 256, k = r % 256;
        float v = (k < FD) ? Wlin[d * FD * FD + k * FD + n]
                           : Wroot[d * FD * FD + (k - FD) * FD + n];
        g_Bmf[i] = __float2half(v);
    }
}

__global__ void k_count(const int* __restrict__ col) {
    int e = blockIdx.x * blockDim.x + threadIdx.x;
    if (e < NE) atomicAdd(&g_degraw[col[e]], 1);
}

__global__ void k_bcount() {
    __shared__ int h[MAXD + 1];
    int tid = threadIdx.x;
    if (tid <= MAXD) h[tid] = 0;
    __syncthreads();
    int i = blockIdx.x * blockDim.x + tid;
    if (i < NN) atomicAdd(&h[min(g_degraw[i], MAXD)], 1);
    __syncthreads();
    if (tid <= MAXD && h[tid]) atomicAdd(&g_bcnt[tid], h[tid]);
}

__global__ void k_scan1() {
    __shared__ int sd[SCB];
    int tid = threadIdx.x;
    int i = blockIdx.x * SCB + tid;
    sd[tid] = (i < NN) ? g_degraw[i] : 0;
    __syncthreads();
    for (int off = SCB / 2; off > 0; off >>= 1) {
        if (tid < off) sd[tid] += sd[tid + off];
        __syncthreads();
    }
    if (tid == 0) g_bsum[blockIdx.x] = sd[0];
}

__global__ void k_scan2() {
    int s = 0;
    for (int b = 0; b < NSCB; b++) { int v = g_bsum[b]; g_bsum[b] = s; s += v; }
    g_off[NN] = s;
    int t = 0;
    for (int d = 0; d <= MAXD; d++) { g_boff[d] = t; t += g_bcnt[d]; }
    g_boff[MAXD + 1] = t;
}

__global__ void k_scan3() {
    __shared__ int sd[SCB];
    int tid = threadIdx.x;
    int i = blockIdx.x * SCB + tid;
    int v = (i < NN) ? g_degraw[i] : 0;
    sd[tid] = v;
    __syncthreads();
    for (int off = 1; off < SCB; off <<= 1) {
        int t = 0;
        if (tid >= off) t = sd[tid - off];
        __syncthreads();
        if (tid >= off) sd[tid] += t;
        __syncthreads();
    }
    if (i < NN) g_off[i] = g_bsum[blockIdx.x] + sd[tid] - v;
}

__global__ void k_bfill() {
    __shared__ int h[MAXD + 1];
    __shared__ int sbase[MAXD + 1];
    int tid = threadIdx.x;
    if (tid <= MAXD) h[tid] = 0;
    __syncthreads();
    int i = blockIdx.x * blockDim.x + tid;
    int d = -1;
    if (i < NN) { d = min(g_degraw[i], MAXD); atomicAdd(&h[d], 1); }
    __syncthreads();
    if (tid <= MAXD) {
        sbase[tid] = h[tid] ? atomicAdd(&g_bcur[tid], h[tid]) : 0;
        h[tid] = 0;
    }
    __syncthreads();
    if (i < NN) {
        int p = atomicAdd(&h[d], 1);
        g_bnodes[g_boff[d] + sbase[d] + p] = i;
    }
}

__global__ void k_fillcsr(const int* __restrict__ row, const int* __restrict__ col) {
    int e = blockIdx.x * blockDim.x + threadIdx.x;
    if (e < NE) {
        int c = col[e];
        int p = atomicAdd(&g_cursor[c], 1);
        g_srcv[g_off[c] + p] = row[e];
    }
}

// ---------------- neighbor sum ----------------
__global__ void k_nsum(const float* __restrict__ Xext, int use_internal) {
    const float* __restrict__ X = use_internal ? g_X : Xext;
    int warp = (blockIdx.x * blockDim.x + threadIdx.x) >> 5;
    int lane = threadIdx.x & 31;
    if (warp >= NN) return;
    int beg = g_off[warp], end = g_off[warp + 1];
    float4 acc = make_float4(0.f, 0.f, 0.f, 0.f);
    for (int e = beg; e < end; e++) {
        int s = g_srcv[e];
        float4 v = *(const float4*)(X + (size_t)s * FD + lane * 4);
        acc.x += v.x; acc.y += v.y; acc.z += v.z; acc.w += v.w;
    }
    *(float4*)(g_H + (size_t)warp * FD + lane * 4) = acc;
}

// ---------------- HMMA GEMM: [P|Q] = E @ Bpq (M64 N256, 2 CTA/SM) ----------------
__global__ void __launch_bounds__(GTP, 2) k_pq_h(const float* __restrict__ Eext, int use_ext) {
    extern __shared__ char sm[];
    const float* __restrict__ Ein = use_ext ? Eext : g_E;
    int tid = threadIdx.x, wid = tid >> 5, lane = tid & 31;
    int warpM = wid & 1, warpN = wid >> 1;   // 2x4; warp tile 32 rows x 64 cols
    int base = blockIdx.x * 64;

    u32 Ahi = s2u(sm), Alo = Ahi + TIL64, Bsm = Alo + TIL64;

    // B full tile via cp.async (256 rows x 128 halfs)
    for (int i = tid; i < 4096; i += GTP) {
        int r = i >> 4, c = i & 15;
        cpa16(Bsm + r * SPB + c * 16, g_Bpq + (size_t)r * FD + c * 8);
    }
    // A: 64 rows f32 -> fp16 hi/lo
    for (int i = tid; i < 2048; i += GTP) {
        int r = i >> 5, c = i & 31;
        int node = base + r;
        float4 v = (node < NN) ? *((const float4*)(Ein + (size_t)node * FD) + c)
                               : make_float4(0.f, 0.f, 0.f, 0.f);
        uint2 hi, lo;
        split4h(v, hi, lo);
        *(uint2*)(sm + r * SPB + c * 8) = hi;
        *(uint2*)(sm + TIL64 + r * SPB + c * 8) = lo;
    }
    cpa_fence();
    __syncthreads();

    float acc[2][8][4];
#pragma unroll
    for (int a = 0; a < 2; a++)
#pragma unroll
        for (int b = 0; b < 8; b++)
#pragma unroll
            for (int cx = 0; cx < 4; cx++) acc[a][b][cx] = 0.f;

    u32 rowsel = lane & 15;
    u32 kx = (lane >> 4) * 16;
    int arow = warpM * 32, brow = warpN * 64;

#pragma unroll
    for (int ks = 0; ks < 8; ks++) {
        u32 kadd = ks * 32 + kx;
        u32 ah[2][4], al[2][4];
#pragma unroll
        for (int mt = 0; mt < 2; mt++) {
            u32 ro = (arow + mt * 16 + rowsel) * SPB + kadd;
            ldmx4(ah[mt], Ahi + ro);
            ldmx4(al[mt], Alo + ro);
        }
#pragma unroll
        for (int bt = 0; bt < 4; bt++) {
            u32 bh[4];
            ldmx4(bh, Bsm + (brow + bt * 16 + rowsel) * SPB + kadd);
#pragma unroll
            for (int mt = 0; mt < 2; mt++)
#pragma unroll
                for (int bi = 0; bi < 2; bi++) {
                    int nt = bt * 2 + bi;
                    mmah(acc[mt][nt], ah[mt], bh[bi], bh[bi + 2]);
                    mmah(acc[mt][nt], al[mt], bh[bi], bh[bi + 2]);
                }
        }
    }

#pragma unroll
    for (int mt = 0; mt < 2; mt++) {
        int r0 = base + warpM * 32 + mt * 16 + (lane >> 2);
#pragma unroll
        for (int nt = 0; nt < 8; nt++) {
            int col = warpN * 64 + nt * 8 + (lane & 3) * 2;
            float* dst = (col < FD) ? g_P : g_Q;
            int c2 = col & (FD - 1);
            if (r0 < NN)
                *(float2*)(dst + (size_t)r0 * FD + c2) = make_float2(acc[mt][nt][0], acc[mt][nt][1]);
            if (r0 + 8 < NN)
                *(float2*)(dst + (size_t)(r0 + 8) * FD + c2) = make_float2(acc[mt][nt][2], acc[mt][nt][3]);
        }
    }
}

// ---------------- HMMA GEMM: MFConv per-bucket (M128 N128, fp16 2-term, 2 CTA/SM) ----------------
__global__ void __launch_bounds__(GTM, 2) k_mf_h(const float* __restrict__ Xext, int use_ext,
                                                 const float* __restrict__ blin,
                                                 float* __restrict__ emb) {
    int d = blockIdx.y;
    int bstart = g_boff[d];
    int bcnt = g_boff[d + 1] - bstart;
    int base = blockIdx.x * 128;
    if (base >= bcnt) return;

    extern __shared__ char sm[];
    __shared__ int s_node[128];
    int tid = threadIdx.x, wid = tid >> 5, lane = tid & 31;
    int warpM = wid & 1, warpN = wid >> 1;   // 2x4; warp tile 64 rows x 32 cols
    if (tid < 128) s_node[tid] = (tid < bcnt - base) ? g_bnodes[bstart + base + tid] : -1;
    __syncthreads();

    u32 Ahi = s2u(sm), Alo = Ahi + TILEB, Bsm = Alo + TILEB;
    const __half* Bw = g_Bmf + (size_t)d * FD * 256;

    float acc[4][4][4];
#pragma unroll
    for (int a = 0; a < 4; a++)
#pragma unroll
        for (int b = 0; b < 4; b++)
#pragma unroll
            for (int cx = 0; cx < 4; cx++) acc[a][b][cx] = 0.f;

    u32 rowsel = lane & 15;
    u32 kx = (lane >> 4) * 16;
    int arow = warpM * 64, brow = warpN * 32;

    for (int chunk = 0; chunk < 2; chunk++) {
        for (int i = tid; i < 2048; i += GTM) {
            int r = i >> 4, c = i & 15;
            cpa16(Bsm + r * SPB + c * 16, Bw + (size_t)r * 256 + chunk * 128 + c * 8);
        }
        const float* __restrict__ Asrc = chunk ? (use_ext ? Xext : g_X) : g_H;
        for (int i = tid; i < 4096; i += GTM) {
            int r = i >> 5, c = i & 31;
            int node = s_node[r];
            float4 v = (node >= 0) ? *((const float4*)(Asrc + (size_t)node * FD) + c)
                                   : make_float4(0.f, 0.f, 0.f, 0.f);
            uint2 hi, lo;
            split4h(v, hi, lo);
            *(uint2*)(sm + r * SPB + c * 8) = hi;
            *(uint2*)(sm + TILEB + r * SPB + c * 8) = lo;
        }
        cpa_fence();
        __syncthreads();

#pragma unroll
        for (int ks = 0; ks < 8; ks++) {
            u32 kadd = ks * 32 + kx;
            u32 ah[4][4], al[4][4];
#pragma unroll
            for (int mt = 0; mt < 4; mt++) {
                u32 ro = (arow + mt * 16 + rowsel) * SPB + kadd;
                ldmx4(ah[mt], Ahi + ro);
                ldmx4(al[mt], Alo + ro);
            }
            u32 bh0[4], bh1[4];
            ldmx4(bh0, Bsm + (brow + rowsel) * SPB + kadd);
            ldmx4(bh1, Bsm + (brow + 16 + rowsel) * SPB + kadd);
#pragma unroll
            for (int mt = 0; mt < 4; mt++) {
                mmah(acc[mt][0], ah[mt], bh0[0], bh0[2]);
                mmah(acc[mt][0], al[mt], bh0[0], bh0[2]);
                mmah(acc[mt][1], ah[mt], bh0[1], bh0[3]);
                mmah(acc[mt][1], al[mt], bh0[1], bh0[3]);
                mmah(acc[mt][2], ah[mt], bh1[0], bh1[2]);
                mmah(acc[mt][2], al[mt], bh1[0], bh1[2]);
                mmah(acc[mt][3], ah[mt], bh1[1], bh1[3]);
                mmah(acc[mt][3], al[mt], bh1[1], bh1[3]);
            }
        }
        __syncthreads();
    }

#pragma unroll
    for (int mt = 0; mt < 4; mt++) {
        int lr = warpM * 64 + mt * 16 + (lane >> 2);
#pragma unroll
        for (int half = 0; half < 2; half++) {
            int node = s_node[lr + half * 8];
            if (node < 0) continue;
#pragma unroll
            for (int nt = 0; nt < 4; nt++) {
                int col = warpN * 32 + nt * 8 + (lane & 3) * 2;
                float2 b = *(const float2*)(blin + (size_t)d * FD + col);
                float v0 = acc[mt][nt][half * 2] + b.x;
                float v1 = acc[mt][nt][half * 2 + 1] + b.y;
                size_t o = (size_t)node * FD + col;
                if (emb) *(float2*)(emb + o) = make_float2(v0, v1);
                *(float2*)(g_X + o) = make_float2(fmaxf(v0, 0.f), fmaxf(v1, 0.f));
            }
        }
    }
}

// ---------------- Edge max aggregation ----------------
__global__ void k_edgemax(const float* __restrict__ bedge, float* __restrict__ emb) {
    int warp = (blockIdx.x * blockDim.x + threadIdx.x) >> 5;
    int lane = threadIdx.x & 31;
    if (warp >= NN) return;
    int beg = g_off[warp], end = g_off[warp + 1];
    float4 m = make_float4(-3.402823466e38f, -3.402823466e38f,
                           -3.402823466e38f, -3.402823466e38f);
    for (int e = beg; e < end; e++) {
        int s = g_srcv[e];
        float4 q = *(const float4*)(g_Q + (size_t)s * FD + lane * 4);
        m.x = fmaxf(m.x, q.x); m.y = fmaxf(m.y, q.y);
        m.z = fmaxf(m.z, q.z); m.w = fmaxf(m.w, q.w);
    }
    float4 val;
    if (end > beg) {
        float4 p = *(const float4*)(g_P + (size_t)warp * FD + lane * 4);
        float4 b = *(const float4*)(bedge + lane * 4);
        val.x = p.x + b.x + m.x; val.y = p.y + b.y + m.y;
        val.z = p.z + b.z + m.z; val.w = p.w + b.w + m.w;
    } else {
        val = make_float4(0.f, 0.f, 0.f, 0.f);
    }
    size_t o = (size_t)warp * FD + lane * 4;
    if (emb) *(float4*)(emb + o) = val;
    float4 r;
    r.x = fmaxf(val.x, 0.f); r.y = fmaxf(val.y, 0.f);
    r.z = fmaxf(val.z, 0.f); r.w = fmaxf(val.w, 0.f);
    *(float4*)(g_E + o) = r;
}

// ---------------- fused graph pooling (warp-parallel edge gather) ----------------
__device__ __forceinline__ int lb_batch(const int* __restrict__ b, int val) {
    int lo = 0, hi = NN;
    while (lo < hi) {
        int mid = (lo + hi) >> 1;
        if (b[mid] < val) lo = mid + 1; else hi = mid;
    }
    return lo;
}

__global__ void k_pool(const int* __restrict__ batch) {
    int g = blockIdx.x;
    int tid = threadIdx.x, w = tid >> 5, lane = tid & 31;
    __shared__ int s_lo, s_hi;
    __shared__ __align__(16) float sred[8][FD];
    if (tid == 0) { s_lo = lb_batch(batch, g); s_hi = lb_batch(batch, g + 1); }
    __syncthreads();
    int lo = s_lo, hi = s_hi;

    // first half: sum over this graph's contiguous CSR edge range of X2relu[src]
    {
        int e0 = g_off[lo], e1 = g_off[hi];
        float4 acc = make_float4(0.f, 0.f, 0.f, 0.f);
        for (int e = e0 + w; e < e1; e += 8) {
            int s = g_srcv[e];
            float4 v = *(const float4*)(g_X + (size_t)s * FD + lane * 4);
            acc.x += v.x; acc.y += v.y; acc.z += v.z; acc.w += v.w;
        }
        *(float4*)&sred[w][lane * 4] = acc;
    }
    __syncthreads();
    if (tid < FD) {
        float s = 0.f;
#pragma unroll
        for (int ww = 0; ww < 8; ww++) s += sred[ww][tid];
        g_G[g * 2 * FD + tid] = s;
    }
    __syncthreads();

    // second half: sum over nodes of degraw * E2relu
    {
        float4 acc = make_float4(0.f, 0.f, 0.f, 0.f);
        for (int i = lo + w; i < hi; i += 8) {
            float dg = (float)g_degraw[i];
            float4 v = *(const float4*)(g_E + (size_t)i * FD + lane * 4);
            acc.x += dg * v.x; acc.y += dg * v.y; acc.z += dg * v.z; acc.w += dg * v.w;
        }
        *(float4*)&sred[w][lane * 4] = acc;
    }
    __syncthreads();
    if (tid < FD) {
        float s = 0.f;
#pragma unroll
        for (int ww = 0; ww < 8; ww++) s += sred[ww][tid];
        g_G[g * 2 * FD + FD + tid] = s;
    }
}

// ---------------- readout MLP ----------------
__global__ void k_mlp(const float* __restrict__ W0, const float* __restrict__ b0,
                      const float* __restrict__ W1, const float* __restrict__ b1,
                      float* __restrict__ out) {
    int g = blockIdx.x;
    int j = threadIdx.x;
    __shared__ float sg[2 * FD];
    __shared__ float sh[HIDN];
    sg[j] = g_G[g * 2 * FD + j];
    __syncthreads();
    float a = b0[j];
#pragma unroll 4
    for (int k = 0; k < 2 * FD; k++) a = fmaf(sg[k], W0[k * HIDN + j], a);
    sh[j] = fmaxf(a, 0.f);
    __syncthreads();
    if (j < ODIM) {
        float o = b1[j];
#pragma unroll 4
        for (int k = 0; k < HIDN; k++) o = fmaf(sh[k], W1[k * ODIM + j], o);
        out[g * ODIM + j] = fmaxf(o, 0.f);
    }
}

// ---------------- zero fill ----------------
__global__ void k_zerotail(float* __restrict__ p, long long n4) {
    long long i = (long long)blockIdx.x * blockDim.x + threadIdx.x;
    if (i < n4) ((float4*)p)[i] = make_float4(0.f, 0.f, 0.f, 0.f);
}

// ---------------- launch ----------------
extern "C" void kernel_launch(void* const* d_in, const int* in_sizes, int n_in,
                              void* d_out, int out_size) {
    const float* x     = (const float*)d_in[0];
    const float* ea    = (const float*)d_in[1];
    const int*   ei    = (const int*)d_in[2];
    const int*   batch = (const int*)d_in[3];
    const float* Wlin  = (const float*)d_in[4];
    const float* blin  = (const float*)d_in[5];
    const float* Wroot = (const float*)d_in[6];
    const float* Wedge = (const float*)d_in[7];
    const float* bedge = (const float*)d_in[8];
    const float* W0    = (const float*)d_in[9];
    const float* b0    = (const float*)d_in[10];
    const float* W1    = (const float*)d_in[11];
    const float* b1    = (const float*)d_in[12];

    float* out      = (float*)d_out;
    float* emb_node = out + NG * ODIM;
    float* emb_edge = emb_node + (size_t)NN * FD;

    const int* row = ei;
    const int* col = ei + NE;

    const int PQ_SMEM = 2 * TIL64 + B256B;   // 104448 B
    const int MF_SMEM = 3 * TILEB;           // 104448 B

    static cudaStream_t sB = nullptr, sC = nullptr;
    static cudaEvent_t evStart, evInit, evCSR, evE2, evCdone;
    if (!sB) {
        cudaStreamCreateWithFlags(&sB, cudaStreamNonBlocking);
        cudaStreamCreateWithFlags(&sC, cudaStreamNonBlocking);
        cudaEventCreateWithFlags(&evStart, cudaEventDisableTiming);
        cudaEventCreateWithFlags(&evInit,  cudaEventDisableTiming);
        cudaEventCreateWithFlags(&evCSR,   cudaEventDisableTiming);
        cudaEventCreateWithFlags(&evE2,    cudaEventDisableTiming);
        cudaEventCreateWithFlags(&evCdone, cudaEventDisableTiming);
        cudaFuncSetAttribute(k_pq_h, cudaFuncAttributeMaxDynamicSharedMemorySize, PQ_SMEM);
        cudaFuncSetAttribute(k_mf_h, cudaFuncAttributeMaxDynamicSharedMemorySize, MF_SMEM);
    }

    dim3 b256(256);
    int gN = (NN + 255) / 256;
    int gE = (NE + 255) / 256;
    int gW = NN / 8;
    dim3 gMF(NT, MAXD + 1);
    long long n4 = (long long)(NE - NN) * FD / 4;

    cudaEventRecord(evStart, 0);

    // sub 0: zerotail (stream C)
    cudaStreamWaitEvent(sC, evStart, 0);
    k_zerotail<<<(unsigned)((n4 + 255) / 256), b256, 0, sC>>>(
        emb_edge + (size_t)NN * FD, n4);
    cudaEventRecord(evCdone, sC);
    // sub 1: initW (main)
    k_initW<<<1408, b256>>>(Wedge, Wlin, Wroot);
    cudaEventRecord(evInit, 0);
    // sub 2: count (main)
    k_count<<<gE, b256>>>(col);
    // sub 3: pq HMMA iter 1 (stream B) — profiled by ncu
    cudaStreamWaitEvent(sB, evInit, 0);
    k_pq_h<<<NT2, GTP, PQ_SMEM, sB>>>(ea, 1);

    // main: rest of CSR/bucket prep
    k_bcount<<<gN, b256>>>();
    k_scan1<<<NSCB, SCB>>>();
    k_scan2<<<1, 1>>>();
    k_scan3<<<NSCB, SCB>>>();
    k_bfill<<<gN, b256>>>();
    k_fillcsr<<<gE, b256>>>(row, col);
    cudaEventRecord(evCSR, 0);

    // stream B: edge path
    cudaStreamWaitEvent(sB, evCSR, 0);
    k_edgemax<<<gW, b256, 0, sB>>>(bedge, nullptr);
    k_pq_h<<<NT2, GTP, PQ_SMEM, sB>>>(nullptr, 0);
    k_edgemax<<<gW, b256, 0, sB>>>(bedge, emb_edge);
    cudaEventRecord(evE2, sB);

    // main: node path
    k_nsum<<<gW, b256>>>(x, 0);
    k_mf_h<<<gMF, GTM, MF_SMEM>>>(x, 1, blin, nullptr);
    k_nsum<<<gW, b256>>>(nullptr, 1);
    k_mf_h<<<gMF, GTM, MF_SMEM>>>(nullptr, 0, blin, emb_node);

    // join + readout (pool gathers X2 directly over CSR edge ranges)
    cudaStreamWaitEvent(0, evE2, 0);
    k_pool<<<NG, b256>>>(batch);
    k_mlp<<<NG, b256>>>(W0, b0, W1, b1, out);
    cudaStreamWaitEvent(0, evCdone, 0);
}

// round 16
// speedup vs baseline: 1.0091x; 1.0091x over previous
#include <cuda_runtime.h>
#include <cuda_fp16.h>

#define NN   50000
#define NE   600000
#define FD   128
#define NG   256
#define HIDN 256
#define ODIM 16
#define MAXD 10
#define SCB  512
#define NSCB ((NN + SCB - 1) / SCB)
#define NT   ((NN + 127) / 128)        // 391 M-tiles
#define SP   136                       // padded smem row stride (halfs)
#define SPB  (SP * 2)                  // 272 bytes
#define TILEB (128 * SPB)              // 34816 B per 128x128 tile
#define B256B (256 * SPB)              // 69632 B per 256x128 tile
#define GT   512                       // pq GEMM threads
#define GTM  256                       // mf GEMM threads

typedef unsigned long long u64;
typedef unsigned int u32;

// ---------------- scratch ----------------
__device__ int   g_degraw[NN];
__device__ int   g_off[NN + 1];
__device__ int   g_cursor[NN];
__device__ int   g_srcv[NE];
__device__ int   g_bcnt[MAXD + 1];
__device__ int   g_boff[MAXD + 2];
__device__ int   g_bcur[MAXD + 1];
__device__ int   g_bnodes[NN];
__device__ int   g_bsum[NSCB];
__device__ float g_X[NN * FD];
__device__ float g_H[NN * FD];
__device__ float g_E[NN * FD];
__device__ float g_P[NN * FD];
__device__ float g_Q[NN * FD];
__device__ float g_G[NG * 2 * FD];
__device__ __half g_Bpq[256 * FD];                 // [n=256][k=128]
__device__ __half g_Bmf[(MAXD + 1) * FD * 256];    // [d][n=128][k=256]

// ---------------- helpers ----------------
__device__ __forceinline__ u32 s2u(const void* p) {
    u32 a; asm("{ .reg .u64 t; cvta.to.shared.u64 t, %1; cvt.u32.u64 %0, t; }" : "=r"(a) : "l"(p));
    return a;
}
__device__ __forceinline__ void ldmx4(u32* r, u32 addr) {
    asm volatile("ldmatrix.sync.aligned.m8n8.x4.shared.b16 {%0,%1,%2,%3}, [%4];"
                 : "=r"(r[0]), "=r"(r[1]), "=r"(r[2]), "=r"(r[3]) : "r"(addr));
}
__device__ __forceinline__ void mmah(float* d, const u32* a, u32 b0, u32 b1) {
    asm volatile("mma.sync.aligned.m16n8k16.row.col.f32.f16.f16.f32 "
                 "{%0,%1,%2,%3}, {%4,%5,%6,%7}, {%8,%9}, {%0,%1,%2,%3};"
                 : "+f"(d[0]), "+f"(d[1]), "+f"(d[2]), "+f"(d[3])
                 : "r"(a[0]), "r"(a[1]), "r"(a[2]), "r"(a[3]), "r"(b0), "r"(b1));
}
__device__ __forceinline__ void cpa16(u32 saddr, const void* g) {
    asm volatile("cp.async.cg.shared.global [%0], [%1], 16;"
                 :: "r"(saddr), "l"(g) : "memory");
}
__device__ __forceinline__ void cpa_commit() {
    asm volatile("cp.async.commit_group;" ::: "memory");
}
__device__ __forceinline__ void cpa_wait1() {
    asm volatile("cp.async.wait_group 1;" ::: "memory");
}
__device__ __forceinline__ void cpa_wait0() {
    asm volatile("cp.async.wait_group 0;" ::: "memory");
}
// split float4 -> fp16 hi (2 u32) and lo (2 u32)
__device__ __forceinline__ void split4h(float4 v, uint2& hi, uint2& lo) {
    __half h0 = __float2half(v.x), h1 = __float2half(v.y);
    __half h2 = __float2half(v.z), h3 = __float2half(v.w);
    __half2 H0 = __halves2half2(h0, h1);
    __half2 H1 = __halves2half2(h2, h3);
    __half2 L0 = __halves2half2(__float2half(v.x - __half2float(h0)),
                                __float2half(v.y - __half2float(h1)));
    __half2 L1 = __halves2half2(__float2half(v.z - __half2float(h2)),
                                __float2half(v.w - __half2float(h3)));
    hi.x = *(u32*)&H0; hi.y = *(u32*)&H1;
    lo.x = *(u32*)&L0; lo.y = *(u32*)&L1;
}

// ---------------- prep ----------------
__global__ void k_initW(const float* __restrict__ Wedge, const float* __restrict__ Wlin,
                        const float* __restrict__ Wroot) {
    int i = blockIdx.x * 256 + threadIdx.x;
    if (i < NN) { g_degraw[i] = 0; g_cursor[i] = 0; }
    if (i <= MAXD) { g_bcnt[i] = 0; g_bcur[i] = 0; }
    if (i < 256 * FD) {
        int n = i / FD, k = i % FD;
        float v = (n < FD) ? (Wedge[k * FD + n] - Wedge[(k + FD) * FD + n])
                           : Wedge[(k + FD) * FD + (n - FD)];
        g_Bpq[i] = __float2half(v);
    }
    if (i < (MAXD + 1) * FD * 256) {
        int d = i / (FD * 256), r = i % (FD * 256);
        int n = r / 256, k = r % 256;
        float v = (k < FD) ? Wlin[d * FD * FD + k * FD + n]
                           : Wroot[d * FD * FD + (k - FD) * FD + n];
        g_Bmf[i] = __float2half(v);
    }
}

__global__ void k_count(const int* __restrict__ col) {
    int e = blockIdx.x * blockDim.x + threadIdx.x;
    if (e < NE) atomicAdd(&g_degraw[col[e]], 1);
}

__global__ void k_bcount() {
    __shared__ int h[MAXD + 1];
    int tid = threadIdx.x;
    if (tid <= MAXD) h[tid] = 0;
    __syncthreads();
    int i = blockIdx.x * blockDim.x + tid;
    if (i < NN) atomicAdd(&h[min(g_degraw[i], MAXD)], 1);
    __syncthreads();
    if (tid <= MAXD && h[tid]) atomicAdd(&g_bcnt[tid], h[tid]);
}

__global__ void k_scan1() {
    __shared__ int sd[SCB];
    int tid = threadIdx.x;
    int i = blockIdx.x * SCB + tid;
    sd[tid] = (i < NN) ? g_degraw[i] : 0;
    __syncthreads();
    for (int off = SCB / 2; off > 0; off >>= 1) {
        if (tid < off) sd[tid] += sd[tid + off];
        __syncthreads();
    }
    if (tid == 0) g_bsum[blockIdx.x] = sd[0];
}

__global__ void k_scan2() {
    int s = 0;
    for (int b = 0; b < NSCB; b++) { int v = g_bsum[b]; g_bsum[b] = s; s += v; }
    g_off[NN] = s;
    int t = 0;
    for (int d = 0; d <= MAXD; d++) { g_boff[d] = t; t += g_bcnt[d]; }
    g_boff[MAXD + 1] = t;
}

__global__ void k_scan3() {
    __shared__ int sd[SCB];
    int tid = threadIdx.x;
    int i = blockIdx.x * SCB + tid;
    int v = (i < NN) ? g_degraw[i] : 0;
    sd[tid] = v;
    __syncthreads();
    for (int off = 1; off < SCB; off <<= 1) {
        int t = 0;
        if (tid >= off) t = sd[tid - off];
        __syncthreads();
        if (tid >= off) sd[tid] += t;
        __syncthreads();
    }
    if (i < NN) g_off[i] = g_bsum[blockIdx.x] + sd[tid] - v;
}

__global__ void k_bfill() {
    __shared__ int h[MAXD + 1];
    __shared__ int sbase[MAXD + 1];
    int tid = threadIdx.x;
    if (tid <= MAXD) h[tid] = 0;
    __syncthreads();
    int i = blockIdx.x * blockDim.x + tid;
    int d = -1;
    if (i < NN) { d = min(g_degraw[i], MAXD); atomicAdd(&h[d], 1); }
    __syncthreads();
    if (tid <= MAXD) {
        sbase[tid] = h[tid] ? atomicAdd(&g_bcur[tid], h[tid]) : 0;
        h[tid] = 0;
    }
    __syncthreads();
    if (i < NN) {
        int p = atomicAdd(&h[d], 1);
        g_bnodes[g_boff[d] + sbase[d] + p] = i;
    }
}

__global__ void k_fillcsr(const int* __restrict__ row, const int* __restrict__ col) {
    int e = blockIdx.x * blockDim.x + threadIdx.x;
    if (e < NE) {
        int c = col[e];
        int p = atomicAdd(&g_cursor[c], 1);
        g_srcv[g_off[c] + p] = row[e];
    }
}

// ---------------- neighbor sum ----------------
__global__ void k_nsum(const float* __restrict__ Xext, int use_internal) {
    const float* __restrict__ X = use_internal ? g_X : Xext;
    int warp = (blockIdx.x * blockDim.x + threadIdx.x) >> 5;
    int lane = threadIdx.x & 31;
    if (warp >= NN) return;
    int beg = g_off[warp], end = g_off[warp + 1];
    float4 acc = make_float4(0.f, 0.f, 0.f, 0.f);
    for (int e = beg; e < end; e++) {
        int s = g_srcv[e];
        float4 v = *(const float4*)(X + (size_t)s * FD + lane * 4);
        acc.x += v.x; acc.y += v.y; acc.z += v.z; acc.w += v.w;
    }
    *(float4*)(g_H + (size_t)warp * FD + lane * 4) = acc;
}

// ---------------- fragment loaders ----------------
__device__ __forceinline__ void loadA2(u32 Ahi, u32 Alo, int rowbase, u32 rowsel, u32 kadd,
                                       u32 ah[2][4], u32 al[2][4]) {
#pragma unroll
    for (int mt = 0; mt < 2; mt++) {
        u32 ro = (rowbase + mt * 16 + rowsel) * SPB + kadd;
        ldmx4(ah[mt], Ahi + ro);
        ldmx4(al[mt], Alo + ro);
    }
}

// ---------------- HMMA GEMM: [P|Q] = E @ Bpq (M128 N256), fp16 2-term, k-halved ----------------
__global__ void __launch_bounds__(GT) k_pq_h(const float* __restrict__ Eext, int use_ext) {
    extern __shared__ char sm[];
    const float* __restrict__ Ein = use_ext ? Eext : g_E;
    int tid = threadIdx.x, wid = tid >> 5, lane = tid & 31;
    int warpM = wid & 3, warpN = wid >> 2;   // 4x4; warp tile 32 rows x 64 cols
    int base = blockIdx.x * 128;

    u32 Ahi = s2u(sm), Alo = Ahi + TILEB, Bsm = Alo + TILEB;

    // B half0 (k 0..63) -> group 0
    for (int i = tid; i < 2048; i += GT) {
        int r = i >> 3, c = i & 7;
        cpa16(Bsm + r * SPB + c * 16, g_Bpq + (size_t)r * FD + c * 8);
    }
    cpa_commit();
    // B half1 (k 64..127) -> group 1
    for (int i = tid; i < 2048; i += GT) {
        int r = i >> 3, c = (i & 7) + 8;
        cpa16(Bsm + r * SPB + c * 16, g_Bpq + (size_t)r * FD + c * 8);
    }
    cpa_commit();

    // A half0 (f32 -> fp16 hi/lo)
    float4 a0[4];
#pragma unroll
    for (int j = 0; j < 4; j++) {
        int i = tid + j * GT;
        int r = i >> 4, c = i & 15;
        int node = base + r;
        a0[j] = (node < NN) ? *((const float4*)(Ein + (size_t)node * FD) + c)
                            : make_float4(0.f, 0.f, 0.f, 0.f);
    }
#pragma unroll
    for (int j = 0; j < 4; j++) {
        int i = tid + j * GT;
        int r = i >> 4, c = i & 15;
        uint2 hi, lo;
        split4h(a0[j], hi, lo);
        *(uint2*)(sm + r * SPB + c * 8) = hi;
        *(uint2*)(sm + TILEB + r * SPB + c * 8) = lo;
    }
    // prefetch A half1 into registers
    float4 a1[4];
#pragma unroll
    for (int j = 0; j < 4; j++) {
        int i = tid + j * GT;
        int r = i >> 4, c = (i & 15) + 16;
        int node = base + r;
        a1[j] = (node < NN) ? *((const float4*)(Ein + (size_t)node * FD) + c)
                            : make_float4(0.f, 0.f, 0.f, 0.f);
    }
    cpa_wait1();
    __syncthreads();

    float acc[2][8][4];
#pragma unroll
    for (int a = 0; a < 2; a++)
#pragma unroll
        for (int b = 0; b < 8; b++)
#pragma unroll
            for (int cx = 0; cx < 4; cx++) acc[a][b][cx] = 0.f;

    u32 rowsel = lane & 15;
    u32 kx = (lane >> 4) * 16;
    int arow = warpM * 32, brow = warpN * 64;

#pragma unroll
    for (int half = 0; half < 2; half++) {
#pragma unroll
        for (int kss = 0; kss < 4; kss++) {
            int ks = half * 4 + kss;
            u32 kadd = ks * 32 + kx;
            u32 ah[2][4], al[2][4];
            loadA2(Ahi, Alo, arow, rowsel, kadd, ah, al);
#pragma unroll
            for (int bt = 0; bt < 4; bt++) {
                u32 bh[4];
                ldmx4(bh, Bsm + (brow + bt * 16 + rowsel) * SPB + kadd);
#pragma unroll
                for (int mt = 0; mt < 2; mt++)
#pragma unroll
                    for (int bi = 0; bi < 2; bi++) {
                        int nt = bt * 2 + bi;
                        mmah(acc[mt][nt], ah[mt], bh[bi], bh[bi + 2]);
                        mmah(acc[mt][nt], al[mt], bh[bi], bh[bi + 2]);
                    }
            }
        }
        if (half == 0) {
#pragma unroll
            for (int j = 0; j < 4; j++) {
                int i = tid + j * GT;
                int r = i >> 4, c = (i & 15) + 16;
                uint2 hi, lo;
                split4h(a1[j], hi, lo);
                *(uint2*)(sm + r * SPB + c * 8) = hi;
                *(uint2*)(sm + TILEB + r * SPB + c * 8) = lo;
            }
            cpa_wait0();
            __syncthreads();
        }
    }

#pragma unroll
    for (int mt = 0; mt < 2; mt++) {
        int r0 = base + warpM * 32 + mt * 16 + (lane >> 2);
#pragma unroll
        for (int nt = 0; nt < 8; nt++) {
            int col = warpN * 64 + nt * 8 + (lane & 3) * 2;
            float* dst = (col < FD) ? g_P : g_Q;
            int c2 = col & (FD - 1);
            if (r0 < NN)
                *(float2*)(dst + (size_t)r0 * FD + c2) = make_float2(acc[mt][nt][0], acc[mt][nt][1]);
            if (r0 + 8 < NN)
                *(float2*)(dst + (size_t)(r0 + 8) * FD + c2) = make_float2(acc[mt][nt][2], acc[mt][nt][3]);
        }
    }
}

// ---------------- HMMA GEMM: MFConv per-bucket (M128 N128, fp16 2-term, 2 CTA/SM) ----------------
__global__ void __launch_bounds__(GTM, 2) k_mf_h(const float* __restrict__ Xext, int use_ext,
                                                 const float* __restrict__ blin,
                                                 float* __restrict__ emb) {
    int d = blockIdx.y;
    int bstart = g_boff[d];
    int bcnt = g_boff[d + 1] - bstart;
    int base = blockIdx.x * 128;
    if (base >= bcnt) return;

    extern __shared__ char sm[];
    __shared__ int s_node[128];
    int tid = threadIdx.x, wid = tid >> 5, lane = tid & 31;
    int warpM = wid & 1, warpN = wid >> 1;   // 2x4; warp tile 64 rows x 32 cols
    if (tid < 128) s_node[tid] = (tid < bcnt - base) ? g_bnodes[bstart + base + tid] : -1;
    __syncthreads();

    u32 Ahi = s2u(sm), Alo = Ahi + TILEB, Bsm = Alo + TILEB;
    const __half* Bw = g_Bmf + (size_t)d * FD * 256;

    float acc[4][4][4];
#pragma unroll
    for (int a = 0; a < 4; a++)
#pragma unroll
        for (int b = 0; b < 4; b++)
#pragma unroll
            for (int cx = 0; cx < 4; cx++) acc[a][b][cx] = 0.f;

    u32 rowsel = lane & 15;
    u32 kx = (lane >> 4) * 16;
    int arow = warpM * 64, brow = warpN * 32;

    for (int chunk = 0; chunk < 2; chunk++) {
        for (int i = tid; i < 2048; i += GTM) {
            int r = i >> 4, c = i & 15;
            cpa16(Bsm + r * SPB + c * 16, Bw + (size_t)r * 256 + chunk * 128 + c * 8);
        }
        const float* __restrict__ Asrc = chunk ? (use_ext ? Xext : g_X) : g_H;
        for (int i = tid; i < 4096; i += GTM) {
            int r = i >> 5, c = i & 31;
            int node = s_node[r];
            float4 v = (node >= 0) ? *((const float4*)(Asrc + (size_t)node * FD) + c)
                                   : make_float4(0.f, 0.f, 0.f, 0.f);
            uint2 hi, lo;
            split4h(v, hi, lo);
            *(uint2*)(sm + r * SPB + c * 8) = hi;
            *(uint2*)(sm + TILEB + r * SPB + c * 8) = lo;
        }
        asm volatile("cp.async.commit_group;" ::: "memory");
        asm volatile("cp.async.wait_group 0;" ::: "memory");
        __syncthreads();

#pragma unroll
        for (int ks = 0; ks < 8; ks++) {
            u32 kadd = ks * 32 + kx;
            u32 ah[4][4], al[4][4];
#pragma unroll
            for (int mt = 0; mt < 4; mt++) {
                u32 ro = (arow + mt * 16 + rowsel) * SPB + kadd;
                ldmx4(ah[mt], Ahi + ro);
                ldmx4(al[mt], Alo + ro);
            }
            u32 bh0[4], bh1[4];
            ldmx4(bh0, Bsm + (brow + rowsel) * SPB + kadd);
            ldmx4(bh1, Bsm + (brow + 16 + rowsel) * SPB + kadd);
#pragma unroll
            for (int mt = 0; mt < 4; mt++) {
                mmah(acc[mt][0], ah[mt], bh0[0], bh0[2]);
                mmah(acc[mt][0], al[mt], bh0[0], bh0[2]);
                mmah(acc[mt][1], ah[mt], bh0[1], bh0[3]);
                mmah(acc[mt][1], al[mt], bh0[1], bh0[3]);
                mmah(acc[mt][2], ah[mt], bh1[0], bh1[2]);
                mmah(acc[mt][2], al[mt], bh1[0], bh1[2]);
                mmah(acc[mt][3], ah[mt], bh1[1], bh1[3]);
                mmah(acc[mt][3], al[mt], bh1[1], bh1[3]);
            }
        }
        __syncthreads();
    }

#pragma unroll
    for (int mt = 0; mt < 4; mt++) {
        int lr = warpM * 64 + mt * 16 + (lane >> 2);
#pragma unroll
        for (int half = 0; half < 2; half++) {
            int node = s_node[lr + half * 8];
            if (node < 0) continue;
#pragma unroll
            for (int nt = 0; nt < 4; nt++) {
                int col = warpN * 32 + nt * 8 + (lane & 3) * 2;
                float2 b = *(const float2*)(blin + (size_t)d * FD + col);
                float v0 = acc[mt][nt][half * 2] + b.x;
                float v1 = acc[mt][nt][half * 2 + 1] + b.y;
                size_t o = (size_t)node * FD + col;
                if (emb) *(float2*)(emb + o) = make_float2(v0, v1);
                *(float2*)(g_X + o) = make_float2(fmaxf(v0, 0.f), fmaxf(v1, 0.f));
            }
        }
    }
}

// ---------------- Edge max aggregation ----------------
__global__ void k_edgemax(const float* __restrict__ bedge, float* __restrict__ emb) {
    int warp = (blockIdx.x * blockDim.x + threadIdx.x) >> 5;
    int lane = threadIdx.x & 31;
    if (warp >= NN) return;
    int beg = g_off[warp], end = g_off[warp + 1];
    float4 m = make_float4(-3.402823466e38f, -3.402823466e38f,
                           -3.402823466e38f, -3.402823466e38f);
    for (int e = beg; e < end; e++) {
        int s = g_srcv[e];
        float4 q = *(const float4*)(g_Q + (size_t)s * FD + lane * 4);
        m.x = fmaxf(m.x, q.x); m.y = fmaxf(m.y, q.y);
        m.z = fmaxf(m.z, q.z); m.w = fmaxf(m.w, q.w);
    }
    float4 val;
    if (end > beg) {
        float4 p = *(const float4*)(g_P + (size_t)warp * FD + lane * 4);
        float4 b = *(const float4*)(bedge + lane * 4);
        val.x = p.x + b.x + m.x; val.y = p.y + b.y + m.y;
        val.z = p.z + b.z + m.z; val.w = p.w + b.w + m.w;
    } else {
        val = make_float4(0.f, 0.f, 0.f, 0.f);
    }
    size_t o = (size_t)warp * FD + lane * 4;
    if (emb) *(float4*)(emb + o) = val;
    float4 r;
    r.x = fmaxf(val.x, 0.f); r.y = fmaxf(val.y, 0.f);
    r.z = fmaxf(val.z, 0.f); r.w = fmaxf(val.w, 0.f);
    *(float4*)(g_E + o) = r;
}

// ---------------- fused graph pooling (warp-parallel edge gather) ----------------
__device__ __forceinline__ int lb_batch(const int* __restrict__ b, int val) {
    int lo = 0, hi = NN;
    while (lo < hi) {
        int mid = (lo + hi) >> 1;
        if (b[mid] < val) lo = mid + 1; else hi = mid;
    }
    return lo;
}

__global__ void k_pool(const int* __restrict__ batch) {
    int g = blockIdx.x;
    int tid = threadIdx.x, w = tid >> 5, lane = tid & 31;
    __shared__ int s_lo, s_hi;
    __shared__ __align__(16) float sred[8][FD];
    if (tid == 0) { s_lo = lb_batch(batch, g); s_hi = lb_batch(batch, g + 1); }
    __syncthreads();
    int lo = s_lo, hi = s_hi;

    // first half: sum over this graph's contiguous CSR edge range of X2relu[src]
    {
        int e0 = g_off[lo], e1 = g_off[hi];
        float4 acc = make_float4(0.f, 0.f, 0.f, 0.f);
        for (int e = e0 + w; e < e1; e += 8) {
            int s = g_srcv[e];
            float4 v = *(const float4*)(g_X + (size_t)s * FD + lane * 4);
            acc.x += v.x; acc.y += v.y; acc.z += v.z; acc.w += v.w;
        }
        *(float4*)&sred[w][lane * 4] = acc;
    }
    __syncthreads();
    if (tid < FD) {
        float s = 0.f;
#pragma unroll
        for (int ww = 0; ww < 8; ww++) s += sred[ww][tid];
        g_G[g * 2 * FD + tid] = s;
    }
    __syncthreads();

    // second half: sum over nodes of degraw * E2relu
    {
        float4 acc = make_float4(0.f, 0.f, 0.f, 0.f);
        for (int i = lo + w; i < hi; i += 8) {
            float dg = (float)g_degraw[i];
            float4 v = *(const float4*)(g_E + (size_t)i * FD + lane * 4);
            acc.x += dg * v.x; acc.y += dg * v.y; acc.z += dg * v.z; acc.w += dg * v.w;
        }
        *(float4*)&sred[w][lane * 4] = acc;
    }
    __syncthreads();
    if (tid < FD) {
        float s = 0.f;
#pragma unroll
        for (int ww = 0; ww < 8; ww++) s += sred[ww][tid];
        g_G[g * 2 * FD + FD + tid] = s;
    }
}

// ---------------- readout MLP ----------------
__global__ void k_mlp(const float* __restrict__ W0, const float* __restrict__ b0,
                      const float* __restrict__ W1, const float* __restrict__ b1,
                      float* __restrict__ out) {
    int g = blockIdx.x;
    int j = threadIdx.x;
    __shared__ float sg[2 * FD];
    __shared__ float sh[HIDN];
    sg[j] = g_G[g * 2 * FD + j];
    __syncthreads();
    float a = b0[j];
#pragma unroll 4
    for (int k = 0; k < 2 * FD; k++) a = fmaf(sg[k], W0[k * HIDN + j], a);
    sh[j] = fmaxf(a, 0.f);
    __syncthreads();
    if (j < ODIM) {
        float o = b1[j];
#pragma unroll 4
        for (int k = 0; k < HIDN; k++) o = fmaf(sh[k], W1[k * ODIM + j], o);
        out[g * ODIM + j] = fmaxf(o, 0.f);
    }
}

// ---------------- zero fill ----------------
__global__ void k_zerotail(float* __restrict__ p, long long n4) {
    long long i = (long long)blockIdx.x * blockDim.x + threadIdx.x;
    if (i < n4) ((float4*)p)[i] = make_float4(0.f, 0.f, 0.f, 0.f);
}

// ---------------- launch ----------------
extern "C" void kernel_launch(void* const* d_in, const int* in_sizes, int n_in,
                              void* d_out, int out_size) {
    const float* x     = (const float*)d_in[0];
    const float* ea    = (const float*)d_in[1];
    const int*   ei    = (const int*)d_in[2];
    const int*   batch = (const int*)d_in[3];
    const float* Wlin  = (const float*)d_in[4];
    const float* blin  = (const float*)d_in[5];
    const float* Wroot = (const float*)d_in[6];
    const float* Wedge = (const float*)d_in[7];
    const float* bedge = (const float*)d_in[8];
    const float* W0    = (const float*)d_in[9];
    const float* b0    = (const float*)d_in[10];
    const float* W1    = (const float*)d_in[11];
    const float* b1    = (const float*)d_in[12];

    float* out      = (float*)d_out;
    float* emb_node = out + NG * ODIM;
    float* emb_edge = emb_node + (size_t)NN * FD;

    const int* row = ei;
    const int* col = ei + NE;

    const int PQ_SMEM = 2 * TILEB + B256B;   // 139264 B
    const int MF_SMEM = 3 * TILEB;           // 104448 B

    static cudaStream_t sB = nullptr, sC = nullptr;
    static cudaEvent_t evStart, evInit, evCSR, evE2, evCdone;
    if (!sB) {
        cudaStreamCreateWithFlags(&sB, cudaStreamNonBlocking);
        cudaStreamCreateWithFlags(&sC, cudaStreamNonBlocking);
        cudaEventCreateWithFlags(&evStart, cudaEventDisableTiming);
        cudaEventCreateWithFlags(&evInit,  cudaEventDisableTiming);
        cudaEventCreateWithFlags(&evCSR,   cudaEventDisableTiming);
        cudaEventCreateWithFlags(&evE2,    cudaEventDisableTiming);
        cudaEventCreateWithFlags(&evCdone, cudaEventDisableTiming);
        cudaFuncSetAttribute(k_pq_h, cudaFuncAttributeMaxDynamicSharedMemorySize, PQ_SMEM);
        cudaFuncSetAttribute(k_mf_h, cudaFuncAttributeMaxDynamicSharedMemorySize, MF_SMEM);
    }

    dim3 b256(256);
    int gN = (NN + 255) / 256;
    int gE = (NE + 255) / 256;
    int gW = NN / 8;
    dim3 gMF(NT, MAXD + 1);
    long long n4 = (long long)(NE - NN) * FD / 4;

    cudaEventRecord(evStart, 0);

    // sub 0: zerotail (stream C)
    cudaStreamWaitEvent(sC, evStart, 0);
    k_zerotail<<<(unsigned)((n4 + 255) / 256), b256, 0, sC>>>(
        emb_edge + (size_t)NN * FD, n4);
    cudaEventRecord(evCdone, sC);
    // sub 1: initW (main)
    k_initW<<<1408, b256>>>(Wedge, Wlin, Wroot);
    cudaEventRecord(evInit, 0);
    // sub 2: count (main)
    k_count<<<gE, b256>>>(col);
    // sub 3: pq HMMA iter 1 (stream B) — profiled by ncu
    cudaStreamWaitEvent(sB, evInit, 0);
    k_pq_h<<<NT, GT, PQ_SMEM, sB>>>(ea, 1);

    // main: rest of CSR/bucket prep
    k_bcount<<<gN, b256>>>();
    k_scan1<<<NSCB, SCB>>>();
    k_scan2<<<1, 1>>>();
    k_scan3<<<NSCB, SCB>>>();
    k_bfill<<<gN, b256>>>();
    k_fillcsr<<<gE, b256>>>(row, col);
    cudaEventRecord(evCSR, 0);

    // stream B: edge path
    cudaStreamWaitEvent(sB, evCSR, 0);
    k_edgemax<<<gW, b256, 0, sB>>>(bedge, nullptr);
    k_pq_h<<<NT, GT, PQ_SMEM, sB>>>(nullptr, 0);
    k_edgemax<<<gW, b256, 0, sB>>>(bedge, emb_edge);
    cudaEventRecord(evE2, sB);

    // main: node path
    k_nsum<<<gW, b256>>>(x, 0);
    k_mf_h<<<gMF, GTM, MF_SMEM>>>(x, 1, blin, nullptr);
    k_nsum<<<gW, b256>>>(nullptr, 1);
    k_mf_h<<<gMF, GTM, MF_SMEM>>>(nullptr, 0, blin, emb_node);

    // join + readout (pool gathers X2 directly over CSR edge ranges)
    cudaStreamWaitEvent(0, evE2, 0);
    k_pool<<<NG, b256>>>(batch);
    k_mlp<<<NG, b256>>>(W0, b0, W1, b1, out);
    cudaStreamWaitEvent(0, evCdone, 0);
}

// round 17
// speedup vs baseline: 1.0729x; 1.0632x over previous
#include <cuda_runtime.h>
#include <cuda_fp16.h>

#define NN   50000
#define NE   600000
#define FD   128
#define NG   256
#define HIDN 256
#define ODIM 16
#define MAXD 10
#define SCB  512
#define NSCB ((NN + SCB - 1) / SCB)
#define NT   ((NN + 127) / 128)        // 391 M-tiles
#define SP   136                       // padded smem row stride (halfs)
#define SPB  (SP * 2)                  // 272 bytes
#define TILEB (128 * SPB)              // 34816 B per 128x128 tile
#define B256B (256 * SPB)              // 69632 B per 256x128 tile
#define GT   512                       // pq GEMM threads
#define GTM  256                       // mf GEMM threads

typedef unsigned long long u64;
typedef unsigned int u32;

// ---------------- scratch ----------------
__device__ int   g_degraw[NN];
__device__ int   g_off[NN + 1];
__device__ int   g_cursor[NN];
__device__ int   g_srcv[NE];
__device__ int   g_bcnt[MAXD + 1];
__device__ int   g_boff[MAXD + 2];
__device__ int   g_bcur[MAXD + 1];
__device__ int   g_bnodes[NN];
__device__ int   g_bsum[NSCB];
__device__ float g_X[NN * FD];
__device__ float g_H[NN * FD];
__device__ float g_E[NN * FD];
__device__ float g_P[NN * FD];
__device__ float g_Q[NN * FD];
__device__ float g_G[NG * 2 * FD];
__device__ __half g_Bpq[256 * FD];                 // [n=256][k=128]
__device__ __half g_Bmf[(MAXD + 1) * FD * 256];    // [d][n=128][k=256]

// ---------------- helpers ----------------
__device__ __forceinline__ u32 s2u(const void* p) {
    u32 a; asm("{ .reg .u64 t; cvta.to.shared.u64 t, %1; cvt.u32.u64 %0, t; }" : "=r"(a) : "l"(p));
    return a;
}
__device__ __forceinline__ void ldmx4(u32* r, u32 addr) {
    asm volatile("ldmatrix.sync.aligned.m8n8.x4.shared.b16 {%0,%1,%2,%3}, [%4];"
                 : "=r"(r[0]), "=r"(r[1]), "=r"(r[2]), "=r"(r[3]) : "r"(addr));
}
__device__ __forceinline__ void mmah(float* d, const u32* a, u32 b0, u32 b1) {
    asm volatile("mma.sync.aligned.m16n8k16.row.col.f32.f16.f16.f32 "
                 "{%0,%1,%2,%3}, {%4,%5,%6,%7}, {%8,%9}, {%0,%1,%2,%3};"
                 : "+f"(d[0]), "+f"(d[1]), "+f"(d[2]), "+f"(d[3])
                 : "r"(a[0]), "r"(a[1]), "r"(a[2]), "r"(a[3]), "r"(b0), "r"(b1));
}
__device__ __forceinline__ void cpa16(u32 saddr, const void* g) {
    asm volatile("cp.async.cg.shared.global [%0], [%1], 16;"
                 :: "r"(saddr), "l"(g) : "memory");
}
__device__ __forceinline__ void cpa_commit() {
    asm volatile("cp.async.commit_group;" ::: "memory");
}
__device__ __forceinline__ void cpa_wait1() {
    asm volatile("cp.async.wait_group 1;" ::: "memory");
}
__device__ __forceinline__ void cpa_wait0() {
    asm volatile("cp.async.wait_group 0;" ::: "memory");
}
// split float4 -> fp16 hi (2 u32) and lo (2 u32)
__device__ __forceinline__ void split4h(float4 v, uint2& hi, uint2& lo) {
    __half h0 = __float2half(v.x), h1 = __float2half(v.y);
    __half h2 = __float2half(v.z), h3 = __float2half(v.w);
    __half2 H0 = __halves2half2(h0, h1);
    __half2 H1 = __halves2half2(h2, h3);
    __half2 L0 = __halves2half2(__float2half(v.x - __half2float(h0)),
                                __float2half(v.y - __half2float(h1)));
    __half2 L1 = __halves2half2(__float2half(v.z - __half2float(h2)),
                                __float2half(v.w - __half2float(h3)));
    hi.x = *(u32*)&H0; hi.y = *(u32*)&H1;
    lo.x = *(u32*)&L0; lo.y = *(u32*)&L1;
}

// ---------------- prep ----------------
__global__ void k_initW(const float* __restrict__ Wedge, const float* __restrict__ Wlin,
                        const float* __restrict__ Wroot) {
    int i = blockIdx.x * 256 + threadIdx.x;
    if (i < NN) { g_degraw[i] = 0; g_cursor[i] = 0; }
    if (i <= MAXD) { g_bcnt[i] = 0; g_bcur[i] = 0; }
    if (i < 256 * FD) {
        int n = i / FD, k = i % FD;
        float v = (n < FD) ? (Wedge[k * FD + n] - Wedge[(k + FD) * FD + n])
                           : Wedge[(k + FD) * FD + (n - FD)];
        g_Bpq[i] = __float2half(v);
    }
    if (i < (MAXD + 1) * FD * 256) {
        int d = i / (FD * 256), r = i % (FD * 256);
        int n = r / 256, k = r % 256;
        float v = (k < FD) ? Wlin[d * FD * FD + k * FD + n]
                           : Wroot[d * FD * FD + (k - FD) * FD + n];
        g_Bmf[i] = __float2half(v);
    }
}

__global__ void k_count(const int* __restrict__ col) {
    int e = blockIdx.x * blockDim.x + threadIdx.x;
    if (e < NE) atomicAdd(&g_degraw[col[e]], 1);
}

// scan1: per-block sums of degraw + fused degree-bucket histogram
__global__ void k_scan1() {
    __shared__ int sd[SCB];
    __shared__ int h[MAXD + 1];
    int tid = threadIdx.x;
    if (tid <= MAXD) h[tid] = 0;
    int i = blockIdx.x * SCB + tid;
    int v = (i < NN) ? g_degraw[i] : 0;
    sd[tid] = v;
    __syncthreads();
    if (i < NN) atomicAdd(&h[min(v, MAXD)], 1);
    for (int off = SCB / 2; off > 0; off >>= 1) {
        if (tid < off) sd[tid] += sd[tid + off];
        __syncthreads();
    }
    if (tid == 0) g_bsum[blockIdx.x] = sd[0];
    if (tid <= MAXD && h[tid]) atomicAdd(&g_bcnt[tid], h[tid]);
}

__global__ void k_scan2() {
    int s = 0;
    for (int b = 0; b < NSCB; b++) { int v = g_bsum[b]; g_bsum[b] = s; s += v; }
    g_off[NN] = s;
    int t = 0;
    for (int d = 0; d <= MAXD; d++) { g_boff[d] = t; t += g_bcnt[d]; }
    g_boff[MAXD + 1] = t;
}

// scan3: per-block exclusive scan with base + fused bucket fill
__global__ void k_scan3() {
    __shared__ int sd[SCB];
    __shared__ int h[MAXD + 1];
    __shared__ int sbase[MAXD + 1];
    int tid = threadIdx.x;
    if (tid <= MAXD) h[tid] = 0;
    int i = blockIdx.x * SCB + tid;
    int v = (i < NN) ? g_degraw[i] : 0;
    sd[tid] = v;
    __syncthreads();
    for (int off = 1; off < SCB; off <<= 1) {
        int t = 0;
        if (tid >= off) t = sd[tid - off];
        __syncthreads();
        if (tid >= off) sd[tid] += t;
        __syncthreads();
    }
    if (i < NN) g_off[i] = g_bsum[blockIdx.x] + sd[tid] - v;
    // fused bucket fill (block-aggregated atomics)
    int d = -1;
    if (i < NN) { d = min(v, MAXD); atomicAdd(&h[d], 1); }
    __syncthreads();
    if (tid <= MAXD) {
        sbase[tid] = h[tid] ? atomicAdd(&g_bcur[tid], h[tid]) : 0;
        h[tid] = 0;
    }
    __syncthreads();
    if (i < NN) {
        int p = atomicAdd(&h[d], 1);
        g_bnodes[g_boff[d] + sbase[d] + p] = i;
    }
}

__global__ void k_fillcsr(const int* __restrict__ row, const int* __restrict__ col) {
    int e = blockIdx.x * blockDim.x + threadIdx.x;
    if (e < NE) {
        int c = col[e];
        int p = atomicAdd(&g_cursor[c], 1);
        g_srcv[g_off[c] + p] = row[e];
    }
}

// ---------------- neighbor sum ----------------
__global__ void k_nsum(const float* __restrict__ Xext, int use_internal) {
    const float* __restrict__ X = use_internal ? g_X : Xext;
    int warp = (blockIdx.x * blockDim.x + threadIdx.x) >> 5;
    int lane = threadIdx.x & 31;
    if (warp >= NN) return;
    int beg = g_off[warp], end = g_off[warp + 1];
    float4 acc = make_float4(0.f, 0.f, 0.f, 0.f);
    for (int e = beg; e < end; e++) {
        int s = g_srcv[e];
        float4 v = *(const float4*)(X + (size_t)s * FD + lane * 4);
        acc.x += v.x; acc.y += v.y; acc.z += v.z; acc.w += v.w;
    }
    *(float4*)(g_H + (size_t)warp * FD + lane * 4) = acc;
}

// ---------------- fragment loaders ----------------
__device__ __forceinline__ void loadA2(u32 Ahi, u32 Alo, int rowbase, u32 rowsel, u32 kadd,
                                       u32 ah[2][4], u32 al[2][4]) {
#pragma unroll
    for (int mt = 0; mt < 2; mt++) {
        u32 ro = (rowbase + mt * 16 + rowsel) * SPB + kadd;
        ldmx4(ah[mt], Ahi + ro);
        ldmx4(al[mt], Alo + ro);
    }
}

// ---------------- HMMA GEMM: [P|Q] = E @ Bpq (M128 N256), fp16 2-term, k-halved ----------------
__global__ void __launch_bounds__(GT) k_pq_h(const float* __restrict__ Eext, int use_ext) {
    extern __shared__ char sm[];
    const float* __restrict__ Ein = use_ext ? Eext : g_E;
    int tid = threadIdx.x, wid = tid >> 5, lane = tid & 31;
    int warpM = wid & 3, warpN = wid >> 2;   // 4x4; warp tile 32 rows x 64 cols
    int base = blockIdx.x * 128;

    u32 Ahi = s2u(sm), Alo = Ahi + TILEB, Bsm = Alo + TILEB;

    // B half0 (k 0..63) -> group 0
    for (int i = tid; i < 2048; i += GT) {
        int r = i >> 3, c = i & 7;
        cpa16(Bsm + r * SPB + c * 16, g_Bpq + (size_t)r * FD + c * 8);
    }
    cpa_commit();
    // B half1 (k 64..127) -> group 1
    for (int i = tid; i < 2048; i += GT) {
        int r = i >> 3, c = (i & 7) + 8;
        cpa16(Bsm + r * SPB + c * 16, g_Bpq + (size_t)r * FD + c * 8);
    }
    cpa_commit();

    // A half0 (f32 -> fp16 hi/lo)
    float4 a0[4];
#pragma unroll
    for (int j = 0; j < 4; j++) {
        int i = tid + j * GT;
        int r = i >> 4, c = i & 15;
        int node = base + r;
        a0[j] = (node < NN) ? *((const float4*)(Ein + (size_t)node * FD) + c)
                            : make_float4(0.f, 0.f, 0.f, 0.f);
    }
#pragma unroll
    for (int j = 0; j < 4; j++) {
        int i = tid + j * GT;
        int r = i >> 4, c = i & 15;
        uint2 hi, lo;
        split4h(a0[j], hi, lo);
        *(uint2*)(sm + r * SPB + c * 8) = hi;
        *(uint2*)(sm + TILEB + r * SPB + c * 8) = lo;
    }
    // prefetch A half1 into registers
    float4 a1[4];
#pragma unroll
    for (int j = 0; j < 4; j++) {
        int i = tid + j * GT;
        int r = i >> 4, c = (i & 15) + 16;
        int node = base + r;
        a1[j] = (node < NN) ? *((const float4*)(Ein + (size_t)node * FD) + c)
                            : make_float4(0.f, 0.f, 0.f, 0.f);
    }
    cpa_wait1();
    __syncthreads();

    float acc[2][8][4];
#pragma unroll
    for (int a = 0; a < 2; a++)
#pragma unroll
        for (int b = 0; b < 8; b++)
#pragma unroll
            for (int cx = 0; cx < 4; cx++) acc[a][b][cx] = 0.f;

    u32 rowsel = lane & 15;
    u32 kx = (lane >> 4) * 16;
    int arow = warpM * 32, brow = warpN * 64;

#pragma unroll
    for (int half = 0; half < 2; half++) {
#pragma unroll
        for (int kss = 0; kss < 4; kss++) {
            int ks = half * 4 + kss;
            u32 kadd = ks * 32 + kx;
            u32 ah[2][4], al[2][4];
            loadA2(Ahi, Alo, arow, rowsel, kadd, ah, al);
#pragma unroll
            for (int bt = 0; bt < 4; bt++) {
                u32 bh[4];
                ldmx4(bh, Bsm + (brow + bt * 16 + rowsel) * SPB + kadd);
#pragma unroll
                for (int mt = 0; mt < 2; mt++)
#pragma unroll
                    for (int bi = 0; bi < 2; bi++) {
                        int nt = bt * 2 + bi;
                        mmah(acc[mt][nt], ah[mt], bh[bi], bh[bi + 2]);
                        mmah(acc[mt][nt], al[mt], bh[bi], bh[bi + 2]);
                    }
            }
        }
        if (half == 0) {
#pragma unroll
            for (int j = 0; j < 4; j++) {
                int i = tid + j * GT;
                int r = i >> 4, c = (i & 15) + 16;
                uint2 hi, lo;
                split4h(a1[j], hi, lo);
                *(uint2*)(sm + r * SPB + c * 8) = hi;
                *(uint2*)(sm + TILEB + r * SPB + c * 8) = lo;
            }
            cpa_wait0();
            __syncthreads();
        }
    }

#pragma unroll
    for (int mt = 0; mt < 2; mt++) {
        int r0 = base + warpM * 32 + mt * 16 + (lane >> 2);
#pragma unroll
        for (int nt = 0; nt < 8; nt++) {
            int col = warpN * 64 + nt * 8 + (lane & 3) * 2;
            float* dst = (col < FD) ? g_P : g_Q;
            int c2 = col & (FD - 1);
            if (r0 < NN)
                *(float2*)(dst + (size_t)r0 * FD + c2) = make_float2(acc[mt][nt][0], acc[mt][nt][1]);
            if (r0 + 8 < NN)
                *(float2*)(dst + (size_t)(r0 + 8) * FD + c2) = make_float2(acc[mt][nt][2], acc[mt][nt][3]);
        }
    }
}

// ---------------- HMMA GEMM: MFConv per-bucket (M128 N128, fp16 2-term, 2 CTA/SM) ----------------
__global__ void __launch_bounds__(GTM, 2) k_mf_h(const float* __restrict__ Xext, int use_ext,
                                                 const float* __restrict__ blin,
                                                 float* __restrict__ emb) {
    int d = blockIdx.y;
    int bstart = g_boff[d];
    int bcnt = g_boff[d + 1] - bstart;
    int base = blockIdx.x * 128;
    if (base >= bcnt) return;

    extern __shared__ char sm[];
    __shared__ int s_node[128];
    int tid = threadIdx.x, wid = tid >> 5, lane = tid & 31;
    int warpM = wid & 1, warpN = wid >> 1;   // 2x4; warp tile 64 rows x 32 cols
    if (tid < 128) s_node[tid] = (tid < bcnt - base) ? g_bnodes[bstart + base + tid] : -1;
    __syncthreads();

    u32 Ahi = s2u(sm), Alo = Ahi + TILEB, Bsm = Alo + TILEB;
    const __half* Bw = g_Bmf + (size_t)d * FD * 256;

    float acc[4][4][4];
#pragma unroll
    for (int a = 0; a < 4; a++)
#pragma unroll
        for (int b = 0; b < 4; b++)
#pragma unroll
            for (int cx = 0; cx < 4; cx++) acc[a][b][cx] = 0.f;

    u32 rowsel = lane & 15;
    u32 kx = (lane >> 4) * 16;
    int arow = warpM * 64, brow = warpN * 32;

    for (int chunk = 0; chunk < 2; chunk++) {
        for (int i = tid; i < 2048; i += GTM) {
            int r = i >> 4, c = i & 15;
            cpa16(Bsm + r * SPB + c * 16, Bw + (size_t)r * 256 + chunk * 128 + c * 8);
        }
        const float* __restrict__ Asrc = chunk ? (use_ext ? Xext : g_X) : g_H;
        for (int i = tid; i < 4096; i += GTM) {
            int r = i >> 5, c = i & 31;
            int node = s_node[r];
            float4 v = (node >= 0) ? *((const float4*)(Asrc + (size_t)node * FD) + c)
                                   : make_float4(0.f, 0.f, 0.f, 0.f);
            uint2 hi, lo;
            split4h(v, hi, lo);
            *(uint2*)(sm + r * SPB + c * 8) = hi;
            *(uint2*)(sm + TILEB + r * SPB + c * 8) = lo;
        }
        asm volatile("cp.async.commit_group;" ::: "memory");
        asm volatile("cp.async.wait_group 0;" ::: "memory");
        __syncthreads();

#pragma unroll
        for (int ks = 0; ks < 8; ks++) {
            u32 kadd = ks * 32 + kx;
            u32 ah[4][4], al[4][4];
#pragma unroll
            for (int mt = 0; mt < 4; mt++) {
                u32 ro = (arow + mt * 16 + rowsel) * SPB + kadd;
                ldmx4(ah[mt], Ahi + ro);
                ldmx4(al[mt], Alo + ro);
            }
            u32 bh0[4], bh1[4];
            ldmx4(bh0, Bsm + (brow + rowsel) * SPB + kadd);
            ldmx4(bh1, Bsm + (brow + 16 + rowsel) * SPB + kadd);
#pragma unroll
            for (int mt = 0; mt < 4; mt++) {
                mmah(acc[mt][0], ah[mt], bh0[0], bh0[2]);
                mmah(acc[mt][0], al[mt], bh0[0], bh0[2]);
                mmah(acc[mt][1], ah[mt], bh0[1], bh0[3]);
                mmah(acc[mt][1], al[mt], bh0[1], bh0[3]);
                mmah(acc[mt][2], ah[mt], bh1[0], bh1[2]);
                mmah(acc[mt][2], al[mt], bh1[0], bh1[2]);
                mmah(acc[mt][3], ah[mt], bh1[1], bh1[3]);
                mmah(acc[mt][3], al[mt], bh1[1], bh1[3]);
            }
        }
        __syncthreads();
    }

#pragma unroll
    for (int mt = 0; mt < 4; mt++) {
        int lr = warpM * 64 + mt * 16 + (lane >> 2);
#pragma unroll
        for (int half = 0; half < 2; half++) {
            int node = s_node[lr + half * 8];
            if (node < 0) continue;
#pragma unroll
            for (int nt = 0; nt < 4; nt++) {
                int col = warpN * 32 + nt * 8 + (lane & 3) * 2;
                float2 b = *(const float2*)(blin + (size_t)d * FD + col);
                float v0 = acc[mt][nt][half * 2] + b.x;
                float v1 = acc[mt][nt][half * 2 + 1] + b.y;
                size_t o = (size_t)node * FD + col;
                if (emb) *(float2*)(emb + o) = make_float2(v0, v1);
                *(float2*)(g_X + o) = make_float2(fmaxf(v0, 0.f), fmaxf(v1, 0.f));
            }
        }
    }
}

// ---------------- Edge max aggregation ----------------
__global__ void k_edgemax(const float* __restrict__ bedge, float* __restrict__ emb) {
    int warp = (blockIdx.x * blockDim.x + threadIdx.x) >> 5;
    int lane = threadIdx.x & 31;
    if (warp >= NN) return;
    int beg = g_off[warp], end = g_off[warp + 1];
    float4 m = make_float4(-3.402823466e38f, -3.402823466e38f,
                           -3.402823466e38f, -3.402823466e38f);
    for (int e = beg; e < end; e++) {
        int s = g_srcv[e];
        float4 q = *(const float4*)(g_Q + (size_t)s * FD + lane * 4);
        m.x = fmaxf(m.x, q.x); m.y = fmaxf(m.y, q.y);
        m.z = fmaxf(m.z, q.z); m.w = fmaxf(m.w, q.w);
    }
    float4 val;
    if (end > beg) {
        float4 p = *(const float4*)(g_P + (size_t)warp * FD + lane * 4);
        float4 b = *(const float4*)(bedge + lane * 4);
        val.x = p.x + b.x + m.x; val.y = p.y + b.y + m.y;
        val.z = p.z + b.z + m.z; val.w = p.w + b.w + m.w;
    } else {
        val = make_float4(0.f, 0.f, 0.f, 0.f);
    }
    size_t o = (size_t)warp * FD + lane * 4;
    if (emb) *(float4*)(emb + o) = val;
    float4 r;
    r.x = fmaxf(val.x, 0.f); r.y = fmaxf(val.y, 0.f);
    r.z = fmaxf(val.z, 0.f); r.w = fmaxf(val.w, 0.f);
    *(float4*)(g_E + o) = r;
}

// ---------------- graph pooling (simple; round-13 proven) ----------------
__device__ __forceinline__ int lb_batch(const int* __restrict__ b, int val) {
    int lo = 0, hi = NN;
    while (lo < hi) {
        int mid = (lo + hi) >> 1;
        if (b[mid] < val) lo = mid + 1; else hi = mid;
    }
    return lo;
}

__global__ void k_pool(const int* __restrict__ batch) {
    int g = blockIdx.x;
    int f = threadIdx.x;
    __shared__ int s_lo, s_hi;
    if (f == 0) { s_lo = lb_batch(batch, g); s_hi = lb_batch(batch, g + 1); }
    __syncthreads();
    int lo = s_lo, hi = s_hi;
    float acc = 0.f;
    if (f < FD) {
#pragma unroll 4
        for (int i = lo; i < hi; i++) acc += g_H[(size_t)i * FD + f];
    } else {
        int ff = f - FD;
#pragma unroll 4
        for (int i = lo; i < hi; i++)
            acc += (float)g_degraw[i] * g_E[(size_t)i * FD + ff];
    }
    g_G[g * 2 * FD + f] = acc;
}

// ---------------- readout MLP ----------------
__global__ void k_mlp(const float* __restrict__ W0, const float* __restrict__ b0,
                      const float* __restrict__ W1, const float* __restrict__ b1,
                      float* __restrict__ out) {
    int g = blockIdx.x;
    int j = threadIdx.x;
    __shared__ float sg[2 * FD];
    __shared__ float sh[HIDN];
    sg[j] = g_G[g * 2 * FD + j];
    __syncthreads();
    float a = b0[j];
#pragma unroll 4
    for (int k = 0; k < 2 * FD; k++) a = fmaf(sg[k], W0[k * HIDN + j], a);
    sh[j] = fmaxf(a, 0.f);
    __syncthreads();
    if (j < ODIM) {
        float o = b1[j];
#pragma unroll 4
        for (int k = 0; k < HIDN; k++) o = fmaf(sh[k], W1[k * ODIM + j], o);
        out[g * ODIM + j] = fmaxf(o, 0.f);
    }
}

// ---------------- zero fill ----------------
__global__ void k_zerotail(float* __restrict__ p, long long n4) {
    long long i = (long long)blockIdx.x * blockDim.x + threadIdx.x;
    if (i < n4) ((float4*)p)[i] = make_float4(0.f, 0.f, 0.f, 0.f);
}

// ---------------- launch ----------------
extern "C" void kernel_launch(void* const* d_in, const int* in_sizes, int n_in,
                              void* d_out, int out_size) {
    const float* x     = (const float*)d_in[0];
    const float* ea    = (const float*)d_in[1];
    const int*   ei    = (const int*)d_in[2];
    const int*   batch = (const int*)d_in[3];
    const float* Wlin  = (const float*)d_in[4];
    const float* blin  = (const float*)d_in[5];
    const float* Wroot = (const float*)d_in[6];
    const float* Wedge = (const float*)d_in[7];
    const float* bedge = (const float*)d_in[8];
    const float* W0    = (const float*)d_in[9];
    const float* b0    = (const float*)d_in[10];
    const float* W1    = (const float*)d_in[11];
    const float* b1    = (const float*)d_in[12];

    float* out      = (float*)d_out;
    float* emb_node = out + NG * ODIM;
    float* emb_edge = emb_node + (size_t)NN * FD;

    const int* row = ei;
    const int* col = ei + NE;

    const int PQ_SMEM = 2 * TILEB + B256B;   // 139264 B
    const int MF_SMEM = 3 * TILEB;           // 104448 B

    static cudaStream_t sB = nullptr, sC = nullptr;
    static cudaEvent_t evStart, evInit, evCSR, evE2, evCdone;
    if (!sB) {
        cudaStreamCreateWithFlags(&sB, cudaStreamNonBlocking);
        cudaStreamCreateWithFlags(&sC, cudaStreamNonBlocking);
        cudaEventCreateWithFlags(&evStart, cudaEventDisableTiming);
        cudaEventCreateWithFlags(&evInit,  cudaEventDisableTiming);
        cudaEventCreateWithFlags(&evCSR,   cudaEventDisableTiming);
        cudaEventCreateWithFlags(&evE2,    cudaEventDisableTiming);
        cudaEventCreateWithFlags(&evCdone, cudaEventDisableTiming);
        cudaFuncSetAttribute(k_pq_h, cudaFuncAttributeMaxDynamicSharedMemorySize, PQ_SMEM);
        cudaFuncSetAttribute(k_mf_h, cudaFuncAttributeMaxDynamicSharedMemorySize, MF_SMEM);
    }

    dim3 b256(256);
    int gN = (NN + 255) / 256;
    int gE = (NE + 255) / 256;
    int gW = NN / 8;
    dim3 gMF(NT, MAXD + 1);
    long long n4 = (long long)(NE - NN) * FD / 4;

    cudaEventRecord(evStart, 0);

    // sub 0: zerotail (stream C)
    cudaStreamWaitEvent(sC, evStart, 0);
    k_zerotail<<<(unsigned)((n4 + 255) / 256), b256, 0, sC>>>(
        emb_edge + (size_t)NN * FD, n4);
    cudaEventRecord(evCdone, sC);
    // sub 1: initW (main)
    k_initW<<<1408, b256>>>(Wedge, Wlin, Wroot);
    cudaEventRecord(evInit, 0);
    // sub 2: count (main)
    k_count<<<gE, b256>>>(col);
    // sub 3: pq HMMA iter 1 (stream B) — profiled by ncu
    cudaStreamWaitEvent(sB, evInit, 0);
    k_pq_h<<<NT, GT, PQ_SMEM, sB>>>(ea, 1);

    // main: rest of CSR/bucket prep (bcount fused into scan1, bfill into scan3)
    k_scan1<<<NSCB, SCB>>>();
    k_scan2<<<1, 1>>>();
    k_scan3<<<NSCB, SCB>>>();
    k_fillcsr<<<gE, b256>>>(row, col);
    cudaEventRecord(evCSR, 0);

    // stream B: edge path
    cudaStreamWaitEvent(sB, evCSR, 0);
    k_edgemax<<<gW, b256, 0, sB>>>(bedge, nullptr);
    k_pq_h<<<NT, GT, PQ_SMEM, sB>>>(nullptr, 0);
    k_edgemax<<<gW, b256, 0, sB>>>(bedge, emb_edge);
    cudaEventRecord(evE2, sB);

    // main: node path
    k_nsum<<<gW, b256>>>(x, 0);
    k_mf_h<<<gMF, GTM, MF_SMEM>>>(x, 1, blin, nullptr);
    k_nsum<<<gW, b256>>>(nullptr, 1);
    k_mf_h<<<gMF, GTM, MF_SMEM>>>(nullptr, 0, blin, emb_node);
    k_nsum<<<gW, b256>>>(nullptr, 1);

    // join + readout
    cudaStreamWaitEvent(0, evE2, 0);
    k_pool<<<NG, b256>>>(batch);
    k_mlp<<<NG, b256>>>(W0, b0, W1, b1, out);
    cudaStreamWaitEvent(0, evCdone, 0);
}